// round 5
// baseline (speedup 1.0000x reference)
#include <cuda_runtime.h>
#include <math.h>

#define BATCH 16
#define NPTS  4096
#define NSIDES (BATCH * 2)           // 32 point sets (batch x {pred,target})
#define NB 512                       // x-buckets
#define XMIN (-8.0f)
#define BW (16.0f / NB)              // 0.03125
#define INVBW ((float)NB / 16.0f)    // 32

#define SCAN_THREADS 256
#define CHUNKS (NPTS / SCAN_THREADS) // 16
#define NPART (CHUNKS * BATCH * 2)   // 512

// Bucket-sorted copies of each point set (sorted by x, bucket-granular).
__device__ float  g_sx[NSIDES][NPTS];
__device__ float2 g_syz[NSIDES][NPTS];
__device__ int    g_bstart[NSIDES][NB + 1];
__device__ float  g_part[NPART];
__device__ float  g_total[1];

__device__ __forceinline__ int bucket_of(float x) {
    int bk = (int)fmaxf((x - XMIN) * INVBW, 0.0f);
    return min(NB - 1, bk);
}

// One block per (batch, side): counting sort by x-bucket.
// Within-bucket order is nondeterministic (atomic scatter) but the scan
// kernel's result is invariant to it (min over a set + bucket-granular
// continue/stop decisions).
__global__ __launch_bounds__(512)
void sort_kernel(const float* __restrict__ pred,
                 const float* __restrict__ target) {
    __shared__ int hist[NB], scanbuf[NB], cursor[NB];
    const int side = blockIdx.x;          // b*2 + s
    const int b = side >> 1, s = side & 1;
    const float* pts = (s == 0 ? pred : target) + (size_t)b * NPTS * 3;
    const int tid = threadIdx.x;

    hist[tid] = 0;
    __syncthreads();
    for (int p = tid; p < NPTS; p += 512)
        atomicAdd(&hist[bucket_of(pts[p * 3])], 1);
    __syncthreads();

    // inclusive Hillis-Steele scan over NB==512 entries
    scanbuf[tid] = hist[tid];
    __syncthreads();
    for (int off = 1; off < NB; off <<= 1) {
        int v = (tid >= off) ? scanbuf[tid - off] : 0;
        __syncthreads();
        scanbuf[tid] += v;
        __syncthreads();
    }
    int st = scanbuf[tid] - hist[tid];    // exclusive start
    cursor[tid] = st;
    g_bstart[side][tid] = st;
    if (tid == 0) g_bstart[side][NB] = NPTS;
    __syncthreads();

    for (int p = tid; p < NPTS; p += 512) {
        float x = pts[p * 3 + 0];
        float y = pts[p * 3 + 1];
        float z = pts[p * 3 + 2];
        int pos = atomicAdd(&cursor[bucket_of(x)], 1);
        g_sx[side][pos] = x;
        g_syz[side][pos] = make_float2(y, z);
    }
}

// Pruned NN scan. One thread per (sorted) source row; targets for this
// (batch,dir) staged in shared. Walk buckets outward from the home bucket;
// a side stops when (edge distance)^2 exceeds the current min. Bound is the
// exact reverse-triangle inequality d2 >= (x_i - x_j)^2 >= edge^2.
__global__ __launch_bounds__(SCAN_THREADS)
void scan_kernel() {
    __shared__ float  sx[NPTS];           // 16KB
    __shared__ float2 syz[NPTS];          // 32KB  (48KB total, reused below)

    const int chunk = blockIdx.x;
    const int b     = blockIdx.y;
    const int dir   = blockIdx.z;
    const int srcSide = b * 2 + dir;        // dir0: rows = pred
    const int tgtSide = b * 2 + (dir ^ 1);

    for (int p = threadIdx.x; p < NPTS; p += SCAN_THREADS) {
        sx[p]  = g_sx[tgtSide][p];
        syz[p] = g_syz[tgtSide][p];
    }
    __syncthreads();

    const int row = chunk * SCAN_THREADS + threadIdx.x;
    const float kx = g_sx[srcSide][row];
    const float2 kyz = g_syz[srcSide][row];
    const int* __restrict__ bst = g_bstart[tgtSide];

    float m = __int_as_float(0x7F800000);   // +inf

#define EVAL(h) do {                                             \
        float dx = sx[h] - kx;                                   \
        float2 tyz = syz[h];                                     \
        float dy = tyz.x - kyz.x;                                \
        float dz = tyz.y - kyz.y;                                \
        float d2 = fmaf(dx, dx, fmaf(dy, dy, dz * dz));          \
        m = fminf(m, d2);                                        \
    } while (0)

    const int hb = bucket_of(kx);
    {
        int e0 = bst[hb], e1 = bst[hb + 1];
        for (int h = e0; h < e1; h++) EVAL(h);
    }
    int rs = hb + 1, ls = hb - 1;
    bool rA = rs < NB, lA = ls >= 0;
    while (rA || lA) {
        if (rA) {
            float e = (XMIN + rs * BW) - kx;     // >= 0
            if (e * e > m) { rA = false; }
            else {
                int e0 = bst[rs], e1 = bst[rs + 1];
                for (int h = e0; h < e1; h++) EVAL(h);
                rA = (++rs < NB);
            }
        }
        if (lA) {
            float e = kx - (XMIN + (ls + 1) * BW);  // >= 0
            if (e * e > m) { lA = false; }
            else {
                int e0 = bst[ls], e1 = bst[ls + 1];
                for (int h = e0; h < e1; h++) EVAL(h);
                lA = (--ls >= 0);
            }
        }
    }
#undef EVAL

    float sroot = sqrtf(m);                 // m >= 0 by construction

    // Block sum (reuse sx after everyone is done scanning)
    __syncthreads();
    sx[threadIdx.x] = sroot;
    __syncthreads();
    for (int o = SCAN_THREADS / 2; o > 0; o >>= 1) {
        if (threadIdx.x < o) sx[threadIdx.x] += sx[threadIdx.x + o];
        __syncthreads();
    }
    if (threadIdx.x == 0)
        g_part[chunk + CHUNKS * (b + BATCH * dir)] = sx[0];
}

// Deterministic fixed-slot combines.
__global__ void reduce_kernel() {
    __shared__ float ssum[NPART];
    ssum[threadIdx.x] = g_part[threadIdx.x];
    __syncthreads();
    for (int o = NPART / 2; o > 0; o >>= 1) {
        if (threadIdx.x < o) ssum[threadIdx.x] += ssum[threadIdx.x + o];
        __syncthreads();
    }
    if (threadIdx.x == 0) g_total[0] = ssum[0];
}

__global__ void final_kernel(float* __restrict__ out) {
    out[0] = g_total[0] * (1.0f / (2.0f * BATCH * NPTS));
}

extern "C" void kernel_launch(void* const* d_in, const int* in_sizes, int n_in,
                              void* d_out, int out_size) {
    const float* pred   = (const float*)d_in[0];
    const float* target = (const float*)d_in[1];
    float* out = (float*)d_out;

    sort_kernel<<<NSIDES, 512>>>(pred, target);          // launch 1

    dim3 grid(CHUNKS, BATCH, 2);                         // 512 blocks
    scan_kernel<<<grid, SCAN_THREADS>>>();               // launch 2

    reduce_kernel<<<1, NPART>>>();                       // launch 3
    final_kernel<<<1, 1>>>(out);                         // launch 4
}